// round 1
// baseline (speedup 1.0000x reference)
#include <cuda_runtime.h>
#include <cstdint>
#include <math.h>

// ---------------- problem-scale device scratch (static, no allocation) ----------------
#define NMAX 40960
__device__ float4 g_p4[NMAX];      // x, y, z, |p|^2
__device__ int    g_anchors[8192];
__device__ double g_terms[8192];

#define KK 20
#define INFF __int_as_float(0x7f800000)

// ---------------- prep: SoA float4 with precomputed |p|^2 ----------------
__global__ void prep_kernel(const float* __restrict__ pos, int N) {
    int j = blockIdx.x * blockDim.x + threadIdx.x;
    if (j < N) {
        float x = pos[3*j], y = pos[3*j+1], z = pos[3*j+2];
        float n2 = __fadd_rn(__fadd_rn(__fmul_rn(x,x), __fmul_rn(y,y)), __fmul_rn(z,z));
        g_p4[j] = make_float4(x, y, z, n2);
    }
}

// ---------------- FPS: 8-CTA cluster, register-resident points ----------------
#define FCT  8
#define FTPB 512
#define FTOT (FCT*FTPB)   // 4096 threads
#define FP   10           // ceil(40000/4096)

__device__ __forceinline__ unsigned fps_mapa(unsigned addr, unsigned rank) {
    unsigned r;
    asm("mapa.shared::cluster.u32 %0, %1, %2;" : "=r"(r) : "r"(addr), "r"(rank));
    return r;
}
__device__ __forceinline__ unsigned smem_u32_(const void* p) {
    return (unsigned)__cvta_generic_to_shared(p);
}
__device__ __forceinline__ void cluster_sync_() {
    asm volatile("barrier.cluster.arrive.aligned;\n\tbarrier.cluster.wait.aligned;" ::: "memory");
}

__global__ void __cluster_dims__(FCT,1,1) fps_kernel(int N, int nA) {
    __shared__ unsigned long long s_part[2][FCT];   // double-buffered cluster partials
    __shared__ unsigned long long s_wred[FTPB/32];

    int tid  = threadIdx.x;
    unsigned rank; asm("mov.u32 %0, %%cluster_ctarank;" : "=r"(rank));
    int gt   = (int)rank * FTPB + tid;
    int lane = tid & 31, wid = tid >> 5;

    float px[FP], py[FP], pz[FP], md[FP];
    float4 a0 = g_p4[0];
    float bv = -1.0f; int bi = 0x7fffffff;

    #pragma unroll
    for (int s = 0; s < FP; s++) {
        int gi = s*FTOT + gt;
        if (gi < N) {
            float4 q = g_p4[gi];
            px[s]=q.x; py[s]=q.y; pz[s]=q.z;
            float dx=q.x-a0.x, dy=q.y-a0.y, dz=q.z-a0.z;
            float d = dx*dx + dy*dy + dz*dz;
            md[s] = d;
            if (d > bv) { bv = d; bi = gi; }
        } else md[s] = -1.0f;
    }
    if (rank == 0 && tid == 0) g_anchors[0] = 0;

    unsigned laddr = smem_u32_(&s_part[0][0]);
    int buf = 0;
    for (int it = 1; it < nA; ++it) {
        // pack (value desc, index asc) into one u64 so max() == argmax-with-first-tie
        unsigned long long key = ((unsigned long long)__float_as_uint(bv) << 32)
                               | (unsigned)(0xFFFFFFFFu - (unsigned)bi);
        #pragma unroll
        for (int o = 16; o > 0; o >>= 1) {
            unsigned long long k2 = __shfl_xor_sync(0xFFFFFFFFu, key, o);
            if (k2 > key) key = k2;
        }
        if (lane == 0) s_wred[wid] = key;
        __syncthreads();
        if (wid == 0) {
            unsigned long long k = (lane < FTPB/32) ? s_wred[lane] : 0ull;
            #pragma unroll
            for (int o = 16; o > 0; o >>= 1) {
                unsigned long long k2 = __shfl_xor_sync(0xFFFFFFFFu, k, o);
                if (k2 > k) k = k2;
            }
            if (lane == 0) {
                unsigned ad = laddr + (unsigned)((buf*FCT + (int)rank) * 8);
                #pragma unroll
                for (int r = 0; r < FCT; r++) {
                    unsigned ra = fps_mapa(ad, (unsigned)r);
                    asm volatile("st.shared::cluster.u64 [%0], %1;" :: "r"(ra), "l"(k) : "memory");
                }
            }
        }
        cluster_sync_();   // release/acquire orders the DSMEM stores

        unsigned long long wk = s_part[buf][0];
        #pragma unroll
        for (int r = 1; r < FCT; r++) {
            unsigned long long k2 = s_part[buf][r];
            if (k2 > wk) wk = k2;
        }
        int widx = (int)(0xFFFFFFFFu - (unsigned)wk);
        if (rank == 0 && tid == 0) g_anchors[it] = widx;

        float4 ap = g_p4[widx];   // uniform load, L2-resident
        bv = -1.0f; bi = 0x7fffffff;
        #pragma unroll
        for (int s = 0; s < FP; s++) {
            int gi = s*FTOT + gt;
            if (gi < N) {
                float dx=px[s]-ap.x, dy=py[s]-ap.y, dz=pz[s]-ap.z;
                float d = dx*dx + dy*dy + dz*dz;
                float m = fminf(md[s], d);
                md[s] = m;
                if (m > bv) { bv = m; bi = gi; }
            }
        }
        buf ^= 1;
    }
}

// ---------------- KNN + PCA + per-anchor loss term: one warp per anchor ----------------
__device__ __forceinline__ double wsum_d(double v) {
    #pragma unroll
    for (int o = 16; o > 0; o >>= 1) v += __shfl_xor_sync(0xFFFFFFFFu, v, o);
    return v;
}

__global__ void knn_loss_kernel(const float* __restrict__ vec_pred, int N, int nA) {
    int wid  = threadIdx.x >> 5;
    int lane = threadIdx.x & 31;
    int i = blockIdx.x * (blockDim.x >> 5) + wid;
    if (i >= nA) return;

    int a = g_anchors[i];
    float4 ap = g_p4[a];
    float na2 = ap.w;

    float vv[KK]; int ii[KK];
    #pragma unroll
    for (int k = 0; k < KK; k++) { vv[k] = INFF; ii[k] = 0x7fffffff; }

    int steps = N >> 5;
    #pragma unroll 4
    for (int s = 0; s < steps; s++) {
        int j = (s << 5) + lane;
        float4 q = g_p4[j];
        float dot = fmaf(ap.z, q.z, fmaf(ap.y, q.y, ap.x*q.x));
        float d2 = (na2 - 2.0f*dot) + q.w;               // reference's expansion
        if (d2 < vv[KK-1]) {
            float cd = d2; int cj = j;
            #pragma unroll
            for (int k = 0; k < KK; k++) {
                if (cd < vv[k]) { float tv=vv[k]; int ti=ii[k]; vv[k]=cd; ii[k]=cj; cd=tv; cj=ti; }
            }
        }
    }
    // tail (N not multiple of 32) — not hit for N=40000, kept for safety
    int rem = N - (steps << 5);
    if (rem > 0 && lane < rem) {
        int j = (steps << 5) + lane;
        float4 q = g_p4[j];
        float dot = fmaf(ap.z, q.z, fmaf(ap.y, q.y, ap.x*q.x));
        float d2 = (na2 - 2.0f*dot) + q.w;
        if (d2 < vv[KK-1]) {
            float cd = d2; int cj = j;
            #pragma unroll
            for (int k = 0; k < KK; k++) {
                if (cd < vv[k]) { float tv=vv[k]; int ti=ii[k]; vv[k]=cd; ii[k]=cj; cd=tv; cj=ti; }
            }
        }
    }

    // 20-round warp merge; ties -> lower index (matches jax top_k)
    int nbr = -1;
    for (int r = 0; r < KK; r++) {
        unsigned m = __float_as_uint(vv[0]);
        m = (m & 0x80000000u) ? ~m : (m | 0x80000000u);  // monotone float->uint (handles d2<0)
        unsigned long long key = ((unsigned long long)m << 32) | (unsigned)ii[0];
        #pragma unroll
        for (int o = 16; o > 0; o >>= 1) {
            unsigned long long k2 = __shfl_xor_sync(0xFFFFFFFFu, key, o);
            if (k2 < key) key = k2;
        }
        int widx = (int)(unsigned)key;
        if (lane == r) nbr = widx;
        if (ii[0] == widx) {   // winner lane consumes head
            #pragma unroll
            for (int k = 0; k < KK-1; k++) { vv[k]=vv[k+1]; ii[k]=ii[k+1]; }
            vv[KK-1] = INFF; ii[KK-1] = 0x7fffffff;
        }
    }

    // gather neighbors (lanes 0..19), covariance in double
    double x=0.0, y=0.0, z=0.0;
    if (lane < KK) { float4 q = g_p4[nbr]; x=q.x; y=q.y; z=q.z; }
    double sx = wsum_d(x), sy = wsum_d(y), sz = wsum_d(z);
    double mx = sx/KK, my = sy/KK, mz = sz/KK;
    double cx = (lane<KK) ? x-mx : 0.0;
    double cy = (lane<KK) ? y-my : 0.0;
    double cz = (lane<KK) ? z-mz : 0.0;
    double xx = wsum_d(cx*cx), xy = wsum_d(cx*cy), xz = wsum_d(cx*cz);
    double yy = wsum_d(cy*cy), yz = wsum_d(cy*cz), zz = wsum_d(cz*cz);

    if (lane == 0) {
        double A=xx, B=yy, C=zz, D=xy, E=xz, F=yz;
        double p1 = D*D + E*E + F*F;
        double q3 = (A+B+C)/3.0;
        double p2 = (A-q3)*(A-q3) + (B-q3)*(B-q3) + (C-q3)*(C-q3) + 2.0*p1;
        double p  = sqrt(p2/6.0);
        double lam;
        if (p > 0.0) {
            double ip = 1.0/p;
            double b00=(A-q3)*ip, b11=(B-q3)*ip, b22=(C-q3)*ip;
            double b01=D*ip, b02=E*ip, b12=F*ip;
            double det = b00*(b11*b22 - b12*b12)
                       - b01*(b01*b22 - b12*b02)
                       + b02*(b01*b12 - b11*b02);
            double rr = det*0.5;
            rr = fmin(1.0, fmax(-1.0, rr));
            lam = q3 + 2.0*p*cos(acos(rr)/3.0);   // largest eigenvalue
        } else lam = q3;

        // eigenvector: cross products of rows of (C - lam I), pick largest
        double r0x=A-lam, r0y=D,     r0z=E;
        double r1x=D,     r1y=B-lam, r1z=F;
        double r2x=E,     r2y=F,     r2z=C-lam;
        double c1x=r0y*r1z-r0z*r1y, c1y=r0z*r1x-r0x*r1z, c1z=r0x*r1y-r0y*r1x;
        double c2x=r0y*r2z-r0z*r2y, c2y=r0z*r2x-r0x*r2z, c2z=r0x*r2y-r0y*r2x;
        double c3x=r1y*r2z-r1z*r2y, c3y=r1z*r2x-r1x*r2z, c3z=r1x*r2y-r1y*r2x;
        double n1=c1x*c1x+c1y*c1y+c1z*c1z;
        double n2=c2x*c2x+c2y*c2y+c2z*c2z;
        double n3=c3x*c3x+c3y*c3y+c3z*c3z;
        double vx=c1x, vy=c1y, vz=c1z, bn=n1;
        if (n2 > bn) { vx=c2x; vy=c2y; vz=c2z; bn=n2; }
        if (n3 > bn) { vx=c3x; vy=c3y; vz=c3z; bn=n3; }
        if (bn < 1e-300) { vx=1.0; vy=0.0; vz=0.0; bn=1.0; }
        double inv = rsqrt(bn);
        vx*=inv; vy*=inv; vz*=inv;

        const float* vp = vec_pred + 3*i;   // indexed by anchor RANK, per reference
        double ax=vp[0], ay=vp[1], az=vp[2];
        double nrm = sqrt(ax*ax + ay*ay + az*az);
        if (nrm < 1e-8) nrm = 1e-8;
        double dt = ax*vx + ay*vy + az*vz;
        double ac = fabs(dt)/nrm;           // |b|=1 after normalization
        g_terms[i] = log(ac + 1e-6);
    }
}

// ---------------- final deterministic reduction ----------------
__global__ void reduce_kernel(int nA, float* __restrict__ out) {
    __shared__ double sm[32];
    int tid = threadIdx.x;
    double s = 0.0;
    for (int i = tid; i < nA; i += blockDim.x) s += g_terms[i];
    s = wsum_d(s);
    if ((tid & 31) == 0) sm[tid >> 5] = s;
    __syncthreads();
    if (tid < 32) {
        double v = (tid < (int)(blockDim.x >> 5)) ? sm[tid] : 0.0;
        v = wsum_d(v);
        if (tid == 0) out[0] = (float)(-v / (double)nA);
    }
}

// ---------------- launch ----------------
extern "C" void kernel_launch(void* const* d_in, const int* in_sizes, int n_in,
                              void* d_out, int out_size) {
    const float* vec_pred = (const float*)d_in[0];
    const float* pos      = (const float*)d_in[1];
    int N  = in_sizes[1] / 3;
    int nA = (int)ceil(0.1 * (double)N);   // replicate np.ceil(FPS_RATIO*N) in double

    prep_kernel<<<(N + 255)/256, 256>>>(pos, N);
    fps_kernel<<<FCT, FTPB>>>(N, nA);
    int wpb = 8;  // warps per block
    knn_loss_kernel<<<(nA + wpb - 1)/wpb, 32*wpb>>>(vec_pred, N, nA);
    reduce_kernel<<<1, 512>>>(nA, (float*)d_out);
}

// round 2
// speedup vs baseline: 1.1899x; 1.1899x over previous
#include <cuda_runtime.h>
#include <cstdint>
#include <math.h>

// ---------------- problem-scale device scratch (static, no allocation) ----------------
#define NMAX 40960
__device__ float4 g_p4[NMAX];      // x, y, z, |p|^2
__device__ int    g_anchors[8192];
__device__ double g_terms[8192];

#define KK 20
#define INFF __int_as_float(0x7f800000)
typedef unsigned long long ull;

// ---------------- prep: SoA float4 with precomputed |p|^2 ----------------
__global__ void prep_kernel(const float* __restrict__ pos, int N) {
    int j = blockIdx.x * blockDim.x + threadIdx.x;
    if (j < N) {
        float x = pos[3*j], y = pos[3*j+1], z = pos[3*j+2];
        float n2 = __fadd_rn(__fadd_rn(__fmul_rn(x,x), __fmul_rn(y,y)), __fmul_rn(z,z));
        g_p4[j] = make_float4(x, y, z, n2);
    }
}

// ---------------- FPS: 8-CTA cluster, register-resident points, mbarrier exchange ----------------
#define FCT  8
#define FTPB 512
#define FTOT (FCT*FTPB)   // 4096 threads
#define FP   10           // ceil(40000/4096)
#define NPAIR (FP/2)

__device__ __forceinline__ unsigned fps_mapa(unsigned addr, unsigned rank) {
    unsigned r;
    asm("mapa.shared::cluster.u32 %0, %1, %2;" : "=r"(r) : "r"(addr), "r"(rank));
    return r;
}
__device__ __forceinline__ unsigned smem_u32_(const void* p) {
    return (unsigned)__cvta_generic_to_shared(p);
}
__device__ __forceinline__ void cluster_sync_() {
    asm volatile("barrier.cluster.arrive.aligned;\n\tbarrier.cluster.wait.aligned;" ::: "memory");
}
__device__ __forceinline__ ull pack2(float lo, float hi) {
    ull v; asm("mov.b64 %0, {%1, %2};" : "=l"(v) : "r"(__float_as_uint(lo)), "r"(__float_as_uint(hi)));
    return v;
}
__device__ __forceinline__ void unpack2(ull v, float &lo, float &hi) {
    unsigned a, b; asm("mov.b64 {%0, %1}, %2;" : "=r"(a), "=r"(b) : "l"(v));
    lo = __uint_as_float(a); hi = __uint_as_float(b);
}
__device__ __forceinline__ ull add2_(ull a, ull b) {
    ull d; asm("add.rn.f32x2 %0, %1, %2;" : "=l"(d) : "l"(a), "l"(b)); return d;
}
__device__ __forceinline__ ull mul2_(ull a, ull b) {
    ull d; asm("mul.rn.f32x2 %0, %1, %2;" : "=l"(d) : "l"(a), "l"(b)); return d;
}
__device__ __forceinline__ ull fma2_(ull a, ull b, ull c) {
    ull d; asm("fma.rn.f32x2 %0, %1, %2, %3;" : "=l"(d) : "l"(a), "l"(b), "l"(c)); return d;
}

__global__ void __cluster_dims__(FCT,1,1) fps_kernel(int N, int nA) {
    extern __shared__ float4 s_pts[];          // [FTPB*FP] point mirror for winner lookup
    __shared__ ull    s_wkey[FTPB/32];         // per-warp block-stage keys
    __shared__ ull    s_xkey[2][FCT];          // exchanged keys (double buffered)
    __shared__ float4 s_xpos[2][FCT];          // exchanged winner positions
    __shared__ ull    s_bar[2];                // mbarriers

    int tid  = threadIdx.x;
    unsigned rank; asm("mov.u32 %0, %%cluster_ctarank;" : "=r"(rank));
    int gt   = (int)rank * FTPB + tid;
    int lane = tid & 31, wid = tid >> 5;

    if (tid == 0) {
        asm volatile("mbarrier.init.shared.b64 [%0], %1;" :: "r"(smem_u32_(&s_bar[0])), "r"(FCT) : "memory");
        asm volatile("mbarrier.init.shared.b64 [%0], %1;" :: "r"(smem_u32_(&s_bar[1])), "r"(FCT) : "memory");
    }

    // register-resident points (packed pairs) + min-distance array
    ull X2[NPAIR], Y2[NPAIR], Z2[NPAIR];
    float md[FP];
    bool has10 = (9*FTOT + gt) < N;

    float4 a0 = g_p4[0];
    float bv = -1.0f; int bi = 0;
    float xs[FP], ys[FP], zs[FP];
    #pragma unroll
    for (int s = 0; s < FP; s++) {
        int gi = s*FTOT + gt;                 // < NMAX always; tail reads zero-init pad
        float4 q = g_p4[gi];
        s_pts[tid*FP + s] = q;                // mirror for winner position lookup
        xs[s]=q.x; ys[s]=q.y; zs[s]=q.z;
        float dx=q.x-a0.x, dy=q.y-a0.y, dz=q.z-a0.z;
        float d = fmaf(dx,dx, fmaf(dy,dy, dz*dz));
        bool valid = (s < 9) || has10;
        md[s] = valid ? d : -1.0f;
        if (valid && d > bv) { bv = d; bi = gi; }
    }
    #pragma unroll
    for (int p = 0; p < NPAIR; p++) {
        X2[p] = pack2(xs[2*p], xs[2*p+1]);
        Y2[p] = pack2(ys[2*p], ys[2*p+1]);
        Z2[p] = pack2(zs[2*p], zs[2*p+1]);
    }
    if (rank == 0 && tid == 0) g_anchors[0] = 0;
    __syncthreads();      // s_pts ready (CTA-local)
    cluster_sync_();      // mbarrier init visible cluster-wide

    int ph0 = 0, ph1 = 0;
    for (int it = 1; it < nA; ++it) {
        int buf = it & 1;
        // ---- warp stage: REDUX argmax (max value, min index on tie) ----
        unsigned vb   = __float_as_uint(bv);                       // bv >= 0 -> monotone
        unsigned wmax = __reduce_max_sync(0xFFFFFFFFu, vb);
        unsigned cand = (vb == wmax) ? (unsigned)bi : 0xFFFFFFFFu;
        unsigned wmin = __reduce_min_sync(0xFFFFFFFFu, cand);
        if (vb == wmax && (unsigned)bi == wmin)
            s_wkey[wid] = ((ull)wmax << 32) | (0xFFFFFFFFu - wmin);
        __syncthreads();

        // ---- block stage + DSMEM exchange (warp0 only) ----
        if (wid == 0) {
            ull k = (lane < FTPB/32) ? s_wkey[lane] : 0ull;
            unsigned kv   = (unsigned)(k >> 32);
            unsigned bmax = __reduce_max_sync(0xFFFFFFFFu, kv);
            unsigned cenc = (kv == bmax) ? (unsigned)(k & 0xFFFFFFFFu) : 0u;
            unsigned benc = __reduce_max_sync(0xFFFFFFFFu, cenc);   // enc = ~idx -> max enc = min idx
            if (lane < FCT) {
                ull blkkey = ((ull)bmax << 32) | benc;
                unsigned blkidx = 0xFFFFFFFFu - benc;
                int tloc = (int)(blkidx & (FTOT-1)) - (int)rank * FTPB;   // owner thread in this CTA
                int sIdx = (int)(blkidx >> 12);
                float4 bp = s_pts[tloc*FP + sIdx];
                // lane r ships this CTA's partial to cluster rank r (parallel all-to-all)
                unsigned kaddr = fps_mapa(smem_u32_(&s_xkey[buf][rank]),  (unsigned)lane);
                unsigned paddr = fps_mapa(smem_u32_(&s_xpos[buf][rank]),  (unsigned)lane);
                unsigned baddr = fps_mapa(smem_u32_(&s_bar[buf]),         (unsigned)lane);
                ull xy = pack2(bp.x, bp.y);
                asm volatile("st.shared::cluster.u64 [%0], %1;" :: "r"(kaddr), "l"(blkkey) : "memory");
                asm volatile("st.shared::cluster.u64 [%0], %1;" :: "r"(paddr), "l"(xy)     : "memory");
                asm volatile("st.shared::cluster.u32 [%0], %1;" :: "r"(paddr + 8), "r"(__float_as_uint(bp.z)) : "memory");
                asm volatile("mbarrier.arrive.release.cluster.shared::cluster.b64 _, [%0];" :: "r"(baddr) : "memory");
            }
        }

        // ---- wait for all 8 partials (acquire, cluster scope) ----
        {
            int par = buf ? ph1 : ph0;
            unsigned ba = smem_u32_(&s_bar[buf]);
            unsigned done;
            do {
                asm volatile("{\n\t.reg .pred p;\n\t"
                             "mbarrier.try_wait.parity.acquire.cluster.shared::cta.b64 p, [%1], %2;\n\t"
                             "selp.b32 %0, 1, 0, p;\n\t}"
                             : "=r"(done) : "r"(ba), "r"(par) : "memory");
            } while (!done);
            if (buf) ph1 ^= 1; else ph0 ^= 1;
        }

        // ---- consume: max over 8 keys (keys unique), track rank ----
        ull k0=s_xkey[buf][0], k1=s_xkey[buf][1], k2=s_xkey[buf][2], k3=s_xkey[buf][3];
        ull k4=s_xkey[buf][4], k5=s_xkey[buf][5], k6=s_xkey[buf][6], k7=s_xkey[buf][7];
        ull ka = k0; int ra = 0; if (k1 > ka) { ka = k1; ra = 1; }
        ull kb = k2; int rb = 2; if (k3 > kb) { kb = k3; rb = 3; }
        ull kc = k4; int rc = 4; if (k5 > kc) { kc = k5; rc = 5; }
        ull kd = k6; int rd = 6; if (k7 > kd) { kd = k7; rd = 7; }
        if (kb > ka) { ka = kb; ra = rb; }
        if (kd > kc) { kc = kd; rc = rd; }
        if (kc > ka) { ka = kc; ra = rc; }
        float4 ap = s_xpos[buf][ra];
        if (rank == 0 && tid == 0) g_anchors[it] = (int)(0xFFFFFFFFu - (unsigned)ka);

        // ---- update min-distances (f32x2 packed) + argmax ----
        ull nax = pack2(-ap.x, -ap.x), nay = pack2(-ap.y, -ap.y), naz = pack2(-ap.z, -ap.z);
        #pragma unroll
        for (int p = 0; p < NPAIR; p++) {
            ull dx2 = add2_(X2[p], nax);
            ull dy2 = add2_(Y2[p], nay);
            ull dz2 = add2_(Z2[p], naz);
            ull dd  = fma2_(dx2, dx2, fma2_(dy2, dy2, mul2_(dz2, dz2)));
            float dlo, dhi; unpack2(dd, dlo, dhi);
            md[2*p]   = fminf(md[2*p],   dlo);
            md[2*p+1] = fminf(md[2*p+1], dhi);
        }
        bv = md[0]; bi = gt;
        #pragma unroll
        for (int s = 1; s < 9; s++) {
            if (md[s] > bv) { bv = md[s]; bi = gt + s*FTOT; }
        }
        if (has10 && md[9] > bv) { bv = md[9]; bi = gt + 9*FTOT; }
    }
}

// ---------------- KNN + PCA + per-anchor loss term: one warp per anchor ----------------
__device__ __forceinline__ double wsum_d(double v) {
    #pragma unroll
    for (int o = 16; o > 0; o >>= 1) v += __shfl_xor_sync(0xFFFFFFFFu, v, o);
    return v;
}

__global__ void knn_loss_kernel(const float* __restrict__ vec_pred, int N, int nA) {
    int wid  = threadIdx.x >> 5;
    int lane = threadIdx.x & 31;
    int i = blockIdx.x * (blockDim.x >> 5) + wid;
    if (i >= nA) return;

    int a = g_anchors[i];
    float4 ap = g_p4[a];
    float na2 = ap.w;

    float vv[KK]; int ii[KK];
    #pragma unroll
    for (int k = 0; k < KK; k++) { vv[k] = INFF; ii[k] = 0x7fffffff; }

    int steps = N >> 5;
    #pragma unroll 4
    for (int s = 0; s < steps; s++) {
        int j = (s << 5) + lane;
        float4 q = g_p4[j];
        float dot = fmaf(ap.z, q.z, fmaf(ap.y, q.y, ap.x*q.x));
        float d2 = (na2 - 2.0f*dot) + q.w;               // reference's expansion
        if (d2 < vv[KK-1]) {
            float cd = d2; int cj = j;
            #pragma unroll
            for (int k = 0; k < KK; k++) {
                if (cd < vv[k]) { float tv=vv[k]; int ti=ii[k]; vv[k]=cd; ii[k]=cj; cd=tv; cj=ti; }
            }
        }
    }
    int rem = N - (steps << 5);
    if (rem > 0 && lane < rem) {
        int j = (steps << 5) + lane;
        float4 q = g_p4[j];
        float dot = fmaf(ap.z, q.z, fmaf(ap.y, q.y, ap.x*q.x));
        float d2 = (na2 - 2.0f*dot) + q.w;
        if (d2 < vv[KK-1]) {
            float cd = d2; int cj = j;
            #pragma unroll
            for (int k = 0; k < KK; k++) {
                if (cd < vv[k]) { float tv=vv[k]; int ti=ii[k]; vv[k]=cd; ii[k]=cj; cd=tv; cj=ti; }
            }
        }
    }

    // 20-round warp merge; ties -> lower index (matches jax top_k)
    int nbr = -1;
    for (int r = 0; r < KK; r++) {
        unsigned m = __float_as_uint(vv[0]);
        m = (m & 0x80000000u) ? ~m : (m | 0x80000000u);
        unsigned long long key = ((unsigned long long)m << 32) | (unsigned)ii[0];
        #pragma unroll
        for (int o = 16; o > 0; o >>= 1) {
            unsigned long long k2 = __shfl_xor_sync(0xFFFFFFFFu, key, o);
            if (k2 < key) key = k2;
        }
        int widx = (int)(unsigned)key;
        if (lane == r) nbr = widx;
        if (ii[0] == widx) {
            #pragma unroll
            for (int k = 0; k < KK-1; k++) { vv[k]=vv[k+1]; ii[k]=ii[k+1]; }
            vv[KK-1] = INFF; ii[KK-1] = 0x7fffffff;
        }
    }

    // gather neighbors (lanes 0..19), covariance in double
    double x=0.0, y=0.0, z=0.0;
    if (lane < KK) { float4 q = g_p4[nbr]; x=q.x; y=q.y; z=q.z; }
    double sx = wsum_d(x), sy = wsum_d(y), sz = wsum_d(z);
    double mx = sx/KK, my = sy/KK, mz = sz/KK;
    double cx = (lane<KK) ? x-mx : 0.0;
    double cy = (lane<KK) ? y-my : 0.0;
    double cz = (lane<KK) ? z-mz : 0.0;
    double xx = wsum_d(cx*cx), xy = wsum_d(cx*cy), xz = wsum_d(cx*cz);
    double yy = wsum_d(cy*cy), yz = wsum_d(cy*cz), zz = wsum_d(cz*cz);

    if (lane == 0) {
        double A=xx, B=yy, C=zz, D=xy, E=xz, F=yz;
        double p1 = D*D + E*E + F*F;
        double q3 = (A+B+C)/3.0;
        double p2 = (A-q3)*(A-q3) + (B-q3)*(B-q3) + (C-q3)*(C-q3) + 2.0*p1;
        double p  = sqrt(p2/6.0);
        double lam;
        if (p > 0.0) {
            double ip = 1.0/p;
            double b00=(A-q3)*ip, b11=(B-q3)*ip, b22=(C-q3)*ip;
            double b01=D*ip, b02=E*ip, b12=F*ip;
            double det = b00*(b11*b22 - b12*b12)
                       - b01*(b01*b22 - b12*b02)
                       + b02*(b01*b12 - b11*b02);
            double rr = det*0.5;
            rr = fmin(1.0, fmax(-1.0, rr));
            lam = q3 + 2.0*p*cos(acos(rr)/3.0);
        } else lam = q3;

        double r0x=A-lam, r0y=D,     r0z=E;
        double r1x=D,     r1y=B-lam, r1z=F;
        double r2x=E,     r2y=F,     r2z=C-lam;
        double c1x=r0y*r1z-r0z*r1y, c1y=r0z*r1x-r0x*r1z, c1z=r0x*r1y-r0y*r1x;
        double c2x=r0y*r2z-r0z*r2y, c2y=r0z*r2x-r0x*r2z, c2z=r0x*r2y-r0y*r2x;
        double c3x=r1y*r2z-r1z*r2y, c3y=r1z*r2x-r1x*r2z, c3z=r1x*r2y-r1y*r2x;
        double n1=c1x*c1x+c1y*c1y+c1z*c1z;
        double n2=c2x*c2x+c2y*c2y+c2z*c2z;
        double n3=c3x*c3x+c3y*c3y+c3z*c3z;
        double vx=c1x, vy=c1y, vz=c1z, bn=n1;
        if (n2 > bn) { vx=c2x; vy=c2y; vz=c2z; bn=n2; }
        if (n3 > bn) { vx=c3x; vy=c3y; vz=c3z; bn=n3; }
        if (bn < 1e-300) { vx=1.0; vy=0.0; vz=0.0; bn=1.0; }
        double inv = rsqrt(bn);
        vx*=inv; vy*=inv; vz*=inv;

        const float* vp = vec_pred + 3*i;
        double ax=vp[0], ay=vp[1], az=vp[2];
        double nrm = sqrt(ax*ax + ay*ay + az*az);
        if (nrm < 1e-8) nrm = 1e-8;
        double dt = ax*vx + ay*vy + az*vz;
        double ac = fabs(dt)/nrm;
        g_terms[i] = log(ac + 1e-6);
    }
}

// ---------------- final deterministic reduction ----------------
__global__ void reduce_kernel(int nA, float* __restrict__ out) {
    __shared__ double sm[32];
    int tid = threadIdx.x;
    double s = 0.0;
    for (int i = tid; i < nA; i += blockDim.x) s += g_terms[i];
    s = wsum_d(s);
    if ((tid & 31) == 0) sm[tid >> 5] = s;
    __syncthreads();
    if (tid < 32) {
        double v = (tid < (int)(blockDim.x >> 5)) ? sm[tid] : 0.0;
        v = wsum_d(v);
        if (tid == 0) out[0] = (float)(-v / (double)nA);
    }
}

// ---------------- launch ----------------
extern "C" void kernel_launch(void* const* d_in, const int* in_sizes, int n_in,
                              void* d_out, int out_size) {
    const float* vec_pred = (const float*)d_in[0];
    const float* pos      = (const float*)d_in[1];
    int N  = in_sizes[1] / 3;
    int nA = (int)ceil(0.1 * (double)N);

    int smem = FTPB * FP * (int)sizeof(float4);   // 80 KB point mirror
    cudaFuncSetAttribute(fps_kernel, cudaFuncAttributeMaxDynamicSharedMemorySize, smem);

    prep_kernel<<<(N + 255)/256, 256>>>(pos, N);
    fps_kernel<<<FCT, FTPB, smem>>>(N, nA);
    int wpb = 8;
    knn_loss_kernel<<<(nA + wpb - 1)/wpb, 32*wpb>>>(vec_pred, N, nA);
    reduce_kernel<<<1, 512>>>(nA, (float*)d_out);
}